// round 2
// baseline (speedup 1.0000x reference)
#include <cuda_runtime.h>

#define NROWS 16384
#define NCOL  1024
#define G     8
#define NBLK  (NROWS / G)   /* 2048 blocks */
#define NTHR  256
#define NWARP (NTHR / 32)
#define NIT   20
#define CSS   64            /* colsum counter stride in floats (256 B) */
#define LOGMIN (-92.10340371976183f)  /* logf(1e-40) */
#define THR   0.05f         /* ALPHA*LAMBD/RHO */
#define SHRK  0.05f         /* (1-ALPHA)*LAMBD */
#define EPSI  1e-10f

__device__ float g_logr0[NROWS * NCOL];
__device__ float g_z[NROWS * NCOL];
__device__ float g_cs[(size_t)NIT * NCOL * CSS];

__global__ void k_zero() {
    g_cs[((size_t)blockIdx.x * NCOL + threadIdx.x) * CSS] = 0.0f;
}

__device__ __forceinline__ float soft(float x) {
    return copysignf(fmaxf(fabsf(x) - THR, 0.0f), x);
}

__device__ __forceinline__ float wredsum(float v) {
#pragma unroll
    for (int o = 16; o > 0; o >>= 1) v += __shfl_xor_sync(0xffffffffu, v, o);
    return v;
}

// Step 0: R_1 = R_0c / rowsum(R_0c); writes log(R_0c); colsum_1 = sum soft(R_1)^2.
// (Z_0 == 0 is implicit — no Z buffer write; step k=1 uses first=1.)
__global__ void __launch_bounds__(NTHR) k_init(const float* __restrict__ r0,
                                               float* __restrict__ R) {
    __shared__ float sp[4][NWARP];
    const int tid  = threadIdx.x;
    const int lane = tid & 31;
    const int wid  = tid >> 5;
    const int col  = tid * 4;
    const size_t rowbase = (size_t)blockIdx.x * G * NCOL + col;

    float4 buf[2];
    float a[2][4], lg[2][4];
    float c4[4] = {0.f, 0.f, 0.f, 0.f};

    buf[0] = *(const float4*)(r0 + rowbase);
    buf[1] = *(const float4*)(r0 + rowbase + NCOL);

    {   // compute row 0
        float t[4] = {buf[0].x, buf[0].y, buf[0].z, buf[0].w};
#pragma unroll
        for (int j = 0; j < 4; ++j) {
            if (t[j] == 0.0f) { a[0][j] = 1e-40f; lg[0][j] = LOGMIN; }
            else              { a[0][j] = t[j];   lg[0][j] = __logf(t[j]); }
        }
        float p = wredsum((a[0][0] + a[0][1]) + (a[0][2] + a[0][3]));
        if (lane == 0) sp[0][wid] = p;
    }

#pragma unroll
    for (int g = 0; g < G; ++g) {
        const int cur = g & 1, nxt = cur ^ 1;
        if (g + 2 < G)
            buf[cur] = *(const float4*)(r0 + rowbase + (size_t)(g + 2) * NCOL);
        if (g + 1 < G) {
            float t[4] = {buf[nxt].x, buf[nxt].y, buf[nxt].z, buf[nxt].w};
#pragma unroll
            for (int j = 0; j < 4; ++j) {
                if (t[j] == 0.0f) { a[nxt][j] = 1e-40f; lg[nxt][j] = LOGMIN; }
                else              { a[nxt][j] = t[j];   lg[nxt][j] = __logf(t[j]); }
            }
            float p = wredsum((a[nxt][0] + a[nxt][1]) + (a[nxt][2] + a[nxt][3]));
            if (lane == 0) sp[(g + 1) & 3][wid] = p;
        }
        __syncthreads();
        float S = 0.f;
#pragma unroll
        for (int w = 0; w < NWARP; ++w) S += sp[g & 3][w];
        float inv = __fdividef(1.0f, S);

        const size_t base = rowbase + (size_t)g * NCOL;
        float rn[4];
#pragma unroll
        for (int j = 0; j < 4; ++j) rn[j] = a[cur][j] * inv;
        *(float4*)(R + base)       = make_float4(rn[0], rn[1], rn[2], rn[3]);
        *(float4*)(g_logr0 + base) = make_float4(lg[cur][0], lg[cur][1], lg[cur][2], lg[cur][3]);
#pragma unroll
        for (int j = 0; j < 4; ++j) { float s = soft(rn[j]); c4[j] += s * s; }
    }
#pragma unroll
    for (int j = 0; j < 4; ++j)
        atomicAdd(&g_cs[((size_t)1 * NCOL + col + j) * CSS], c4[j]);
}

// Step k: (R_k, Z_{k-1}, colsum_k) -> (R_{k+1}, Z_k, colsum_{k+1}).
// Software-pipelined: load row g+2 / compute row g+1 / barrier / finalize row g.
__global__ void __launch_bounds__(NTHR) k_step(float* __restrict__ R,
                                               int k, int first, int last) {
    __shared__ float sp[4][NWARP];
    const int tid  = threadIdx.x;
    const int lane = tid & 31;
    const int wid  = tid >> 5;
    const int col  = tid * 4;
    const size_t rowbase = (size_t)blockIdx.x * G * NCOL + col;

    float sc[4];
#pragma unroll
    for (int j = 0; j < 4; ++j) {
        float cs = g_cs[((size_t)k * NCOL + col + j) * CSS];
        sc[j] = fmaxf(1.0f - SHRK / (sqrtf(cs) + EPSI), 0.0f);
    }

    float4 rb[2], zb[2], lb[2];
    float e[2][4], zp[2][4];
    float c4[4] = {0.f, 0.f, 0.f, 0.f};

    rb[0] = *(const float4*)(R + rowbase);
    lb[0] = *(const float4*)(g_logr0 + rowbase);
    zb[0] = first ? make_float4(0.f, 0.f, 0.f, 0.f)
                  : *(const float4*)(g_z + rowbase);
    rb[1] = *(const float4*)(R + rowbase + NCOL);
    lb[1] = *(const float4*)(g_logr0 + rowbase + NCOL);
    zb[1] = first ? make_float4(0.f, 0.f, 0.f, 0.f)
                  : *(const float4*)(g_z + rowbase + NCOL);

    {   // compute row 0
        float r[4] = {rb[0].x, rb[0].y, rb[0].z, rb[0].w};
        float z[4] = {zb[0].x, zb[0].y, zb[0].z, zb[0].w};
        float l[4] = {lb[0].x, lb[0].y, lb[0].z, lb[0].w};
#pragma unroll
        for (int j = 0; j < 4; ++j) {
            float x  = r[j] + z[j];
            float s  = soft(x);
            float X  = sc[j] * s;
            zp[0][j] = z[j] + r[j] - X;
            float lx = (X == 0.0f) ? LOGMIN : __logf(X);
            e[0][j]  = __expf(0.5f * ((l[j] + lx) - zp[0][j]));
        }
        float p = wredsum((e[0][0] + e[0][1]) + (e[0][2] + e[0][3]));
        if (lane == 0) sp[0][wid] = p;
    }

#pragma unroll
    for (int g = 0; g < G; ++g) {
        const int cur = g & 1, nxt = cur ^ 1;
        if (g + 2 < G) {
            const size_t b2 = rowbase + (size_t)(g + 2) * NCOL;
            rb[cur] = *(const float4*)(R + b2);
            lb[cur] = *(const float4*)(g_logr0 + b2);
            zb[cur] = first ? make_float4(0.f, 0.f, 0.f, 0.f)
                            : *(const float4*)(g_z + b2);
        }
        if (g + 1 < G) {
            float r[4] = {rb[nxt].x, rb[nxt].y, rb[nxt].z, rb[nxt].w};
            float z[4] = {zb[nxt].x, zb[nxt].y, zb[nxt].z, zb[nxt].w};
            float l[4] = {lb[nxt].x, lb[nxt].y, lb[nxt].z, lb[nxt].w};
#pragma unroll
            for (int j = 0; j < 4; ++j) {
                float x    = r[j] + z[j];
                float s    = soft(x);
                float X    = sc[j] * s;
                zp[nxt][j] = z[j] + r[j] - X;
                float lx   = (X == 0.0f) ? LOGMIN : __logf(X);
                e[nxt][j]  = __expf(0.5f * ((l[j] + lx) - zp[nxt][j]));
            }
            float p = wredsum((e[nxt][0] + e[nxt][1]) + (e[nxt][2] + e[nxt][3]));
            if (lane == 0) sp[(g + 1) & 3][wid] = p;
        }
        __syncthreads();
        float S = 0.f;
#pragma unroll
        for (int w = 0; w < NWARP; ++w) S += sp[g & 3][w];
        float inv = __fdividef(1.0f, S);

        const size_t base = rowbase + (size_t)g * NCOL;
        float rn[4];
#pragma unroll
        for (int j = 0; j < 4; ++j) rn[j] = e[cur][j] * inv;
        *(float4*)(R + base) = make_float4(rn[0], rn[1], rn[2], rn[3]);
        if (!last) {
            *(float4*)(g_z + base) =
                make_float4(zp[cur][0], zp[cur][1], zp[cur][2], zp[cur][3]);
#pragma unroll
            for (int j = 0; j < 4; ++j) {
                float s2 = soft(rn[j] + zp[cur][j]);
                c4[j] += s2 * s2;
            }
        }
    }
    if (!last) {
#pragma unroll
        for (int j = 0; j < 4; ++j)
            atomicAdd(&g_cs[((size_t)(k + 1) * NCOL + col + j) * CSS], c4[j]);
    }
}

extern "C" void kernel_launch(void* const* d_in, const int* in_sizes, int n_in,
                              void* d_out, int out_size) {
    const float* r0 = (const float*)d_in[0];
    float* out = (float*)d_out;

    k_zero<<<NIT, NCOL>>>();
    k_init<<<NBLK, NTHR>>>(r0, out);
    for (int k = 1; k < NIT; ++k)
        k_step<<<NBLK, NTHR>>>(out, k, (k == 1) ? 1 : 0, (k == NIT - 1) ? 1 : 0);
}

// round 3
// speedup vs baseline: 1.7441x; 1.7441x over previous
#include <cuda_runtime.h>

#define NROWS 16384
#define NCOL  1024
#define NPAIR (NROWS / 2)     /* 8192 row pairs */
#define NTHR  256
#define NWARP (NTHR / 32)
#define GRID  592             /* 148 SMs x 4 CTAs, persistent */
#define NIT   20
#define CSS   64              /* colsum counter stride in floats (256 B) */
#define THR   0.05f           /* ALPHA*LAMBD/RHO */
#define SHRK  0.05f           /* (1-ALPHA)*LAMBD */
#define EPSI  1e-10f
#define SQMIN 1e-20f          /* sqrt(MIN_VALUE) */

__device__ float g_u[NROWS * NCOL];                  /* u_k = R_k + Z_{k-1} */
__device__ float g_cs[(size_t)NIT * NCOL * CSS];

__global__ void k_zero() {
    g_cs[((size_t)blockIdx.x * NCOL + threadIdx.x) * CSS] = 0.0f;
}

__device__ __forceinline__ float soft(float x) {
    return copysignf(fmaxf(fabsf(x) - THR, 0.0f), x);
}

__device__ __forceinline__ float wredsum(float v) {
#pragma unroll
    for (int o = 16; o > 0; o >>= 1) v += __shfl_xor_sync(0xffffffffu, v, o);
    return v;
}

// u_1 = R_1 = R_0c / rowsum(R_0c)  (Z_0 = 0); colsum_1 = sum soft(u_1)^2.
__global__ void __launch_bounds__(NTHR, 4) k_init(const float* __restrict__ r0) {
    __shared__ float sp[2][2][NWARP];
    const int tid  = threadIdx.x;
    const int lane = tid & 31;
    const int wid  = tid >> 5;
    const int col  = tid * 4;

    float c4[4] = {0.f, 0.f, 0.f, 0.f};

    float4 a0, a1, na0, na1;
    {
        const size_t b = (size_t)blockIdx.x * 2 * NCOL + col;
        a0 = *(const float4*)(r0 + b);
        a1 = *(const float4*)(r0 + b + NCOL);
    }

    int it = 0;
    for (int pair = blockIdx.x; pair < NPAIR; pair += GRID, ++it) {
        const int cur = it & 1;
        float v0[4] = {a0.x, a0.y, a0.z, a0.w};
        float v1[4] = {a1.x, a1.y, a1.z, a1.w};
#pragma unroll
        for (int j = 0; j < 4; ++j) {
            if (v0[j] == 0.0f) v0[j] = 1e-40f;
            if (v1[j] == 0.0f) v1[j] = 1e-40f;
        }
        float p0 = wredsum((v0[0] + v0[1]) + (v0[2] + v0[3]));
        float p1 = wredsum((v1[0] + v1[1]) + (v1[2] + v1[3]));
        if (lane == 0) { sp[cur][0][wid] = p0; sp[cur][1][wid] = p1; }

        int np = pair + GRID; if (np >= NPAIR) np = pair;   // safe redundant prefetch
        {
            const size_t nb = (size_t)np * 2 * NCOL + col;
            na0 = *(const float4*)(r0 + nb);
            na1 = *(const float4*)(r0 + nb + NCOL);
        }
        __syncthreads();
        float S0 = 0.f, S1 = 0.f;
#pragma unroll
        for (int w = 0; w < NWARP; ++w) { S0 += sp[cur][0][w]; S1 += sp[cur][1][w]; }
        const float i0 = __fdividef(1.0f, S0);
        const float i1 = __fdividef(1.0f, S1);

        const size_t base = (size_t)pair * 2 * NCOL + col;
        float r0n[4], r1n[4];
#pragma unroll
        for (int j = 0; j < 4; ++j) { r0n[j] = v0[j] * i0; r1n[j] = v1[j] * i1; }
        *(float4*)(g_u + base)        = make_float4(r0n[0], r0n[1], r0n[2], r0n[3]);
        *(float4*)(g_u + base + NCOL) = make_float4(r1n[0], r1n[1], r1n[2], r1n[3]);
#pragma unroll
        for (int j = 0; j < 4; ++j) {
            float s0 = soft(r0n[j]), s1 = soft(r1n[j]);
            c4[j] += s0 * s0 + s1 * s1;
        }
        a0 = na0; a1 = na1;
    }
#pragma unroll
    for (int j = 0; j < 4; ++j)
        atomicAdd(&g_cs[((size_t)1 * NCOL + col + j) * CSS], c4[j]);
}

// Step k: u_k -> u_{k+1}, colsum_{k+1}; last step writes R_20 to out instead.
__global__ void __launch_bounds__(NTHR, 4) k_step(const float* __restrict__ r0,
                                                  float* __restrict__ out,
                                                  int k, int last) {
    __shared__ float sp[2][2][NWARP];
    const int tid  = threadIdx.x;
    const int lane = tid & 31;
    const int wid  = tid >> 5;
    const int col  = tid * 4;

    float sc[4];
#pragma unroll
    for (int j = 0; j < 4; ++j) {
        float cs = g_cs[((size_t)k * NCOL + col + j) * CSS];
        sc[j] = fmaxf(1.0f - SHRK / (sqrtf(cs) + EPSI), 0.0f);
    }

    float c4[4] = {0.f, 0.f, 0.f, 0.f};
    float4 u0, u1, h0, h1, nu0, nu1, nh0, nh1;
    {
        const size_t b = (size_t)blockIdx.x * 2 * NCOL + col;
        u0 = *(const float4*)(g_u + b);      u1 = *(const float4*)(g_u + b + NCOL);
        h0 = *(const float4*)(r0 + b);       h1 = *(const float4*)(r0 + b + NCOL);
    }

    int it = 0;
    for (int pair = blockIdx.x; pair < NPAIR; pair += GRID, ++it) {
        const int cur = it & 1;
        float uu0[4] = {u0.x, u0.y, u0.z, u0.w};
        float uu1[4] = {u1.x, u1.y, u1.z, u1.w};
        float hh0[4] = {h0.x, h0.y, h0.z, h0.w};
        float hh1[4] = {h1.x, h1.y, h1.z, h1.w};

        float e0[4], e1[4], zp0[4], zp1[4];
#pragma unroll
        for (int j = 0; j < 4; ++j) {
            float s  = soft(uu0[j]);
            float X  = sc[j] * s;
            zp0[j]   = uu0[j] - X;                          // Z_k
            float sx = (X == 0.0f) ? SQMIN : sqrtf(X);      // MIN_VALUE substitution
            float hr = sqrtf(fmaxf(hh0[j], 1e-38f));        // sqrt(R0c)
            e0[j]    = hr * sx * __expf(-0.5f * zp0[j]);
        }
#pragma unroll
        for (int j = 0; j < 4; ++j) {
            float s  = soft(uu1[j]);
            float X  = sc[j] * s;
            zp1[j]   = uu1[j] - X;
            float sx = (X == 0.0f) ? SQMIN : sqrtf(X);
            float hr = sqrtf(fmaxf(hh1[j], 1e-38f));
            e1[j]    = hr * sx * __expf(-0.5f * zp1[j]);
        }
        float p0 = wredsum((e0[0] + e0[1]) + (e0[2] + e0[3]));
        float p1 = wredsum((e1[0] + e1[1]) + (e1[2] + e1[3]));
        if (lane == 0) { sp[cur][0][wid] = p0; sp[cur][1][wid] = p1; }

        int np = pair + GRID; if (np >= NPAIR) np = pair;
        {
            const size_t nb = (size_t)np * 2 * NCOL + col;
            nu0 = *(const float4*)(g_u + nb); nu1 = *(const float4*)(g_u + nb + NCOL);
            nh0 = *(const float4*)(r0 + nb);  nh1 = *(const float4*)(r0 + nb + NCOL);
        }
        __syncthreads();
        float S0 = 0.f, S1 = 0.f;
#pragma unroll
        for (int w = 0; w < NWARP; ++w) { S0 += sp[cur][0][w]; S1 += sp[cur][1][w]; }
        const float i0 = __fdividef(1.0f, S0);
        const float i1 = __fdividef(1.0f, S1);

        const size_t base = (size_t)pair * 2 * NCOL + col;
        float rn0[4], rn1[4];
#pragma unroll
        for (int j = 0; j < 4; ++j) { rn0[j] = e0[j] * i0; rn1[j] = e1[j] * i1; }

        if (last) {
            *(float4*)(out + base)        = make_float4(rn0[0], rn0[1], rn0[2], rn0[3]);
            *(float4*)(out + base + NCOL) = make_float4(rn1[0], rn1[1], rn1[2], rn1[3]);
        } else {
            float un0[4], un1[4];
#pragma unroll
            for (int j = 0; j < 4; ++j) {
                un0[j] = rn0[j] + zp0[j];                   // u_{k+1}
                un1[j] = rn1[j] + zp1[j];
                float s0 = soft(un0[j]), s1 = soft(un1[j]);
                c4[j] += s0 * s0 + s1 * s1;
            }
            *(float4*)(g_u + base)        = make_float4(un0[0], un0[1], un0[2], un0[3]);
            *(float4*)(g_u + base + NCOL) = make_float4(un1[0], un1[1], un1[2], un1[3]);
        }
        u0 = nu0; u1 = nu1; h0 = nh0; h1 = nh1;
    }
    if (!last) {
#pragma unroll
        for (int j = 0; j < 4; ++j)
            atomicAdd(&g_cs[((size_t)(k + 1) * NCOL + col + j) * CSS], c4[j]);
    }
}

extern "C" void kernel_launch(void* const* d_in, const int* in_sizes, int n_in,
                              void* d_out, int out_size) {
    const float* r0 = (const float*)d_in[0];
    float* out = (float*)d_out;

    k_zero<<<NIT, NCOL>>>();
    k_init<<<GRID, NTHR>>>(r0);
    for (int k = 1; k < NIT; ++k)
        k_step<<<GRID, NTHR>>>(r0, out, k, (k == NIT - 1) ? 1 : 0);
}

// round 5
// speedup vs baseline: 2.2893x; 1.3126x over previous
#include <cuda_runtime.h>
#include <cuda_fp16.h>

#define NROWS 16384
#define NCOL  1024
#define NPAIR (NROWS / 2)     /* 8192 row pairs */
#define NTHR  256
#define NWARP (NTHR / 32)
#define GRID  592             /* 148 SMs x 4 CTAs, persistent */
#define NIT   20
#define CSS   64              /* colsum counter stride in floats (256 B) */
#define THR   0.05f           /* ALPHA*LAMBD/RHO */
#define SHRK  0.05f           /* (1-ALPHA)*LAMBD */
#define EPSI  1e-10f
#define SQMIN 1e-20f          /* sqrt(MIN_VALUE) */

__device__ float  g_u[NROWS * NCOL];                 /* u_k = R_k + Z_{k-1} */
__device__ __half g_h[NROWS * NCOL];                 /* fp16 sqrt(R_0c) */
__device__ float  g_cs[(size_t)NIT * NCOL * CSS];

__global__ void k_zero() {
    g_cs[((size_t)blockIdx.x * NCOL + threadIdx.x) * CSS] = 0.0f;
}

__device__ __forceinline__ float soft(float x) {
    return copysignf(fmaxf(fabsf(x) - THR, 0.0f), x);
}

__device__ __forceinline__ float wredsum(float v) {
#pragma unroll
    for (int o = 16; o > 0; o >>= 1) v += __shfl_xor_sync(0xffffffffu, v, o);
    return v;
}

// u_1 = R_1 = R_0c / rowsum(R_0c)  (Z_0 = 0); writes fp16 sqrt(R_0c); colsum_1.
__global__ void __launch_bounds__(NTHR, 4) k_init(const float* __restrict__ r0) {
    __shared__ float sp[2][2][NWARP];
    const int tid  = threadIdx.x;
    const int lane = tid & 31;
    const int wid  = tid >> 5;
    const int col  = tid * 4;

    float c4[4] = {0.f, 0.f, 0.f, 0.f};

    float4 a0, a1, na0, na1;
    {
        const size_t b = (size_t)blockIdx.x * 2 * NCOL + col;
        a0 = *(const float4*)(r0 + b);
        a1 = *(const float4*)(r0 + b + NCOL);
    }

    int it = 0;
    for (int pair = blockIdx.x; pair < NPAIR; pair += GRID, ++it) {
        const int cur = it & 1;
        float v0[4] = {a0.x, a0.y, a0.z, a0.w};
        float v1[4] = {a1.x, a1.y, a1.z, a1.w};
#pragma unroll
        for (int j = 0; j < 4; ++j) {
            if (v0[j] == 0.0f) v0[j] = 1e-40f;
            if (v1[j] == 0.0f) v1[j] = 1e-40f;
        }
        float p0 = wredsum((v0[0] + v0[1]) + (v0[2] + v0[3]));
        float p1 = wredsum((v1[0] + v1[1]) + (v1[2] + v1[3]));
        if (lane == 0) { sp[cur][0][wid] = p0; sp[cur][1][wid] = p1; }

        int np = pair + GRID; if (np >= NPAIR) np = pair;   // safe redundant prefetch
        {
            const size_t nb = (size_t)np * 2 * NCOL + col;
            na0 = *(const float4*)(r0 + nb);
            na1 = *(const float4*)(r0 + nb + NCOL);
        }
        __syncthreads();
        float S0 = 0.f, S1 = 0.f;
#pragma unroll
        for (int w = 0; w < NWARP; ++w) { S0 += sp[cur][0][w]; S1 += sp[cur][1][w]; }
        const float i0 = __fdividef(1.0f, S0);
        const float i1 = __fdividef(1.0f, S1);

        const size_t base = (size_t)pair * 2 * NCOL + col;
        float r0n[4], r1n[4];
#pragma unroll
        for (int j = 0; j < 4; ++j) { r0n[j] = v0[j] * i0; r1n[j] = v1[j] * i1; }
        *(float4*)(g_u + base)        = make_float4(r0n[0], r0n[1], r0n[2], r0n[3]);
        *(float4*)(g_u + base + NCOL) = make_float4(r1n[0], r1n[1], r1n[2], r1n[3]);

        {   // fp16 sqrt(R_0c)
            float q0[4], q1[4];
#pragma unroll
            for (int j = 0; j < 4; ++j) { q0[j] = sqrtf(v0[j]); q1[j] = sqrtf(v1[j]); }
            __half2 ha = __floats2half2_rn(q0[0], q0[1]);
            __half2 hb = __floats2half2_rn(q0[2], q0[3]);
            __half2 hc = __floats2half2_rn(q1[0], q1[1]);
            __half2 hd = __floats2half2_rn(q1[2], q1[3]);
            uint2 pk0, pk1;
            pk0.x = *reinterpret_cast<unsigned*>(&ha);
            pk0.y = *reinterpret_cast<unsigned*>(&hb);
            pk1.x = *reinterpret_cast<unsigned*>(&hc);
            pk1.y = *reinterpret_cast<unsigned*>(&hd);
            *(uint2*)(g_h + base)        = pk0;
            *(uint2*)(g_h + base + NCOL) = pk1;
        }
#pragma unroll
        for (int j = 0; j < 4; ++j) {
            float s0 = soft(r0n[j]), s1 = soft(r1n[j]);
            c4[j] += s0 * s0 + s1 * s1;
        }
        a0 = na0; a1 = na1;
    }
#pragma unroll
    for (int j = 0; j < 4; ++j)
        atomicAdd(&g_cs[((size_t)1 * NCOL + col + j) * CSS], c4[j]);
}

__device__ __forceinline__ void ldh4(const __half* p, float h[4]) {
    uint2 pk = *(const uint2*)p;
    __half2 a = *reinterpret_cast<__half2*>(&pk.x);
    __half2 b = *reinterpret_cast<__half2*>(&pk.y);
    float2 fa = __half22float2(a);
    float2 fb = __half22float2(b);
    h[0] = fa.x; h[1] = fa.y; h[2] = fb.x; h[3] = fb.y;
}

// Step k: u_k -> u_{k+1}, colsum_{k+1}; last step writes R_20 to out.
// e = sqrt(r0c) * (X==0 ? 1e-20 : sqrt(X)) * exp(-z/2)  [factored form — keeps
// the sqrt(r0c) dependence in the X==0 (dominant) case, matching reference].
__global__ void __launch_bounds__(NTHR, 4) k_step(float* __restrict__ out,
                                                  int k, int rev, int last) {
    __shared__ float sp[2][2][NWARP];
    const int tid  = threadIdx.x;
    const int lane = tid & 31;
    const int wid  = tid >> 5;
    const int col  = tid * 4;

    float sc[4];
#pragma unroll
    for (int j = 0; j < 4; ++j) {
        float cs = g_cs[((size_t)k * NCOL + col + j) * CSS];
        sc[j] = fmaxf(1.0f - SHRK / (sqrtf(cs) + EPSI), 0.0f);
    }

    float c4[4] = {0.f, 0.f, 0.f, 0.f};
    float4 u0, u1, nu0, nu1;
    float hh0[4], hh1[4], nh0[4], nh1[4];

    int pair0 = rev ? (NPAIR - 1 - blockIdx.x) : blockIdx.x;
    {
        const size_t b = (size_t)pair0 * 2 * NCOL + col;
        u0 = *(const float4*)(g_u + b);  u1 = *(const float4*)(g_u + b + NCOL);
        ldh4(g_h + b, hh0);              ldh4(g_h + b + NCOL, hh1);
    }

    int it = 0;
    for (int w = blockIdx.x; w < NPAIR; w += GRID, ++it) {
        const int cur  = it & 1;
        const int pair = rev ? (NPAIR - 1 - w) : w;
        float uu0[4] = {u0.x, u0.y, u0.z, u0.w};
        float uu1[4] = {u1.x, u1.y, u1.z, u1.w};

        float e0[4], e1[4], zp0[4], zp1[4];
#pragma unroll
        for (int j = 0; j < 4; ++j) {
            float s  = soft(uu0[j]);
            float X  = sc[j] * s;
            zp0[j]   = uu0[j] - X;                          // Z_k
            float sx = (X == 0.0f) ? SQMIN : sqrtf(X);      // MIN_VALUE substitution
            e0[j]    = hh0[j] * sx * __expf(-0.5f * zp0[j]);
        }
#pragma unroll
        for (int j = 0; j < 4; ++j) {
            float s  = soft(uu1[j]);
            float X  = sc[j] * s;
            zp1[j]   = uu1[j] - X;
            float sx = (X == 0.0f) ? SQMIN : sqrtf(X);
            e1[j]    = hh1[j] * sx * __expf(-0.5f * zp1[j]);
        }
        float p0 = wredsum((e0[0] + e0[1]) + (e0[2] + e0[3]));
        float p1 = wredsum((e1[0] + e1[1]) + (e1[2] + e1[3]));
        if (lane == 0) { sp[cur][0][wid] = p0; sp[cur][1][wid] = p1; }

        int nw = w + GRID; if (nw >= NPAIR) nw = w;          // safe redundant prefetch
        {
            const int npair = rev ? (NPAIR - 1 - nw) : nw;
            const size_t nb = (size_t)npair * 2 * NCOL + col;
            nu0 = *(const float4*)(g_u + nb); nu1 = *(const float4*)(g_u + nb + NCOL);
            ldh4(g_h + nb, nh0);              ldh4(g_h + nb + NCOL, nh1);
        }
        __syncthreads();
        float S0 = 0.f, S1 = 0.f;
#pragma unroll
        for (int ww = 0; ww < NWARP; ++ww) { S0 += sp[cur][0][ww]; S1 += sp[cur][1][ww]; }
        const float i0 = __fdividef(1.0f, S0);
        const float i1 = __fdividef(1.0f, S1);

        const size_t base = (size_t)pair * 2 * NCOL + col;
        float rn0[4], rn1[4];
#pragma unroll
        for (int j = 0; j < 4; ++j) { rn0[j] = e0[j] * i0; rn1[j] = e1[j] * i1; }

        if (last) {
            *(float4*)(out + base)        = make_float4(rn0[0], rn0[1], rn0[2], rn0[3]);
            *(float4*)(out + base + NCOL) = make_float4(rn1[0], rn1[1], rn1[2], rn1[3]);
        } else {
            float un0[4], un1[4];
#pragma unroll
            for (int j = 0; j < 4; ++j) {
                un0[j] = rn0[j] + zp0[j];                   // u_{k+1}
                un1[j] = rn1[j] + zp1[j];
                float s0 = soft(un0[j]), s1 = soft(un1[j]);
                c4[j] += s0 * s0 + s1 * s1;
            }
            *(float4*)(g_u + base)        = make_float4(un0[0], un0[1], un0[2], un0[3]);
            *(float4*)(g_u + base + NCOL) = make_float4(un1[0], un1[1], un1[2], un1[3]);
        }
        u0 = nu0; u1 = nu1;
#pragma unroll
        for (int j = 0; j < 4; ++j) { hh0[j] = nh0[j]; hh1[j] = nh1[j]; }
    }
    if (!last) {
#pragma unroll
        for (int j = 0; j < 4; ++j)
            atomicAdd(&g_cs[((size_t)(k + 1) * NCOL + col + j) * CSS], c4[j]);
    }
}

extern "C" void kernel_launch(void* const* d_in, const int* in_sizes, int n_in,
                              void* d_out, int out_size) {
    const float* r0 = (const float*)d_in[0];
    float* out = (float*)d_out;

    k_zero<<<NIT, NCOL>>>();
    k_init<<<GRID, NTHR>>>(r0);
    for (int k = 1; k < NIT; ++k)
        k_step<<<GRID, NTHR>>>(out, k, k & 1, (k == NIT - 1) ? 1 : 0);
}

// round 6
// speedup vs baseline: 2.4182x; 1.0563x over previous
#include <cuda_runtime.h>
#include <cuda_fp16.h>

#define NROWS 16384
#define NCOL  1024
#define NPAIR (NROWS / 2)     /* 8192 row pairs */
#define NTHR  256
#define NWARP (NTHR / 32)
#define GRID  592             /* 148 SMs x 4 CTAs, persistent */
#define NIT   20
#define CSS   64              /* colsum counter stride in floats (256 B) */
#define THR   0.05f           /* ALPHA*LAMBD/RHO */
#define SHRK  0.05f           /* (1-ALPHA)*LAMBD */
#define EPSI  1e-10f
#define SQMIN 1e-20f          /* sqrt(MIN_VALUE) */

__device__ __half g_u[NROWS * NCOL];                 /* fp16 u_k = R_k + Z_{k-1} */
__device__ __half g_h[NROWS * NCOL];                 /* fp16 sqrt(R_0c) */
__device__ float  g_cs[(size_t)NIT * NCOL * CSS];

__global__ void k_zero() {
    g_cs[((size_t)blockIdx.x * NCOL + threadIdx.x) * CSS] = 0.0f;
}

/* soft threshold as x - clamp(x, -THR, THR): 3 ops, exact */
__device__ __forceinline__ float soft(float x) {
    return x - fminf(fmaxf(x, -THR), THR);
}

__device__ __forceinline__ float wredsum(float v) {
#pragma unroll
    for (int o = 16; o > 0; o >>= 1) v += __shfl_xor_sync(0xffffffffu, v, o);
    return v;
}

__device__ __forceinline__ void ld4h(const __half* p, float f[4]) {
    uint2 pk = *(const uint2*)p;
    __half2 a = *reinterpret_cast<__half2*>(&pk.x);
    __half2 b = *reinterpret_cast<__half2*>(&pk.y);
    float2 fa = __half22float2(a), fb = __half22float2(b);
    f[0] = fa.x; f[1] = fa.y; f[2] = fb.x; f[3] = fb.y;
}

__device__ __forceinline__ void st4h(__half* p, const float f[4]) {
    __half2 a = __floats2half2_rn(f[0], f[1]);
    __half2 b = __floats2half2_rn(f[2], f[3]);
    uint2 pk;
    pk.x = *reinterpret_cast<unsigned*>(&a);
    pk.y = *reinterpret_cast<unsigned*>(&b);
    *(uint2*)p = pk;
}

// u_1 = R_1 = R_0c / rowsum(R_0c)  (Z_0 = 0); writes fp16 u_1, fp16 sqrt(R_0c); colsum_1.
__global__ void __launch_bounds__(NTHR, 4) k_init(const float* __restrict__ r0) {
    __shared__ float sp[2][2][NWARP];
    const int tid  = threadIdx.x;
    const int lane = tid & 31;
    const int wid  = tid >> 5;
    const int col  = tid * 4;

    float c4[4] = {0.f, 0.f, 0.f, 0.f};

    float4 a0, a1, na0, na1;
    {
        const size_t b = (size_t)blockIdx.x * 2 * NCOL + col;
        a0 = *(const float4*)(r0 + b);
        a1 = *(const float4*)(r0 + b + NCOL);
    }

    int it = 0;
    for (int pair = blockIdx.x; pair < NPAIR; pair += GRID, ++it) {
        const int cur = it & 1;
        float v0[4] = {a0.x, a0.y, a0.z, a0.w};
        float v1[4] = {a1.x, a1.y, a1.z, a1.w};
#pragma unroll
        for (int j = 0; j < 4; ++j) {
            if (v0[j] == 0.0f) v0[j] = 1e-40f;
            if (v1[j] == 0.0f) v1[j] = 1e-40f;
        }
        float p0 = wredsum((v0[0] + v0[1]) + (v0[2] + v0[3]));
        float p1 = wredsum((v1[0] + v1[1]) + (v1[2] + v1[3]));
        if (lane == 0) { sp[cur][0][wid] = p0; sp[cur][1][wid] = p1; }

        int np = pair + GRID; if (np >= NPAIR) np = pair;   // safe redundant prefetch
        {
            const size_t nb = (size_t)np * 2 * NCOL + col;
            na0 = *(const float4*)(r0 + nb);
            na1 = *(const float4*)(r0 + nb + NCOL);
        }
        __syncthreads();
        float S0 = 0.f, S1 = 0.f;
#pragma unroll
        for (int w = 0; w < NWARP; ++w) { S0 += sp[cur][0][w]; S1 += sp[cur][1][w]; }
        const float i0 = __fdividef(1.0f, S0);
        const float i1 = __fdividef(1.0f, S1);

        const size_t base = (size_t)pair * 2 * NCOL + col;
        float r0n[4], r1n[4], q0[4], q1[4];
#pragma unroll
        for (int j = 0; j < 4; ++j) {
            r0n[j] = v0[j] * i0;  r1n[j] = v1[j] * i1;
            q0[j]  = sqrtf(v0[j]); q1[j] = sqrtf(v1[j]);
        }
        st4h(g_u + base,        r0n);
        st4h(g_u + base + NCOL, r1n);
        st4h(g_h + base,        q0);
        st4h(g_h + base + NCOL, q1);
#pragma unroll
        for (int j = 0; j < 4; ++j) {
            float s0 = soft(r0n[j]), s1 = soft(r1n[j]);
            c4[j] += s0 * s0 + s1 * s1;
        }
        a0 = na0; a1 = na1;
    }
#pragma unroll
    for (int j = 0; j < 4; ++j)
        atomicAdd(&g_cs[((size_t)1 * NCOL + col + j) * CSS], c4[j]);
}

// Step k: u_k -> u_{k+1}, colsum_{k+1}; last step writes fp32 R_20 to out.
// e = sqrt(r0c) * (X==0 ? 1e-20 : sqrt(X)) * exp(-z/2)   [factored form]
__global__ void __launch_bounds__(NTHR, 4) k_step(float* __restrict__ out,
                                                  int k, int rev, int last) {
    __shared__ float sp[2][2][NWARP];
    const int tid  = threadIdx.x;
    const int lane = tid & 31;
    const int wid  = tid >> 5;
    const int col  = tid * 4;

    float sc[4];
#pragma unroll
    for (int j = 0; j < 4; ++j) {
        float cs = g_cs[((size_t)k * NCOL + col + j) * CSS];
        sc[j] = fmaxf(1.0f - SHRK / (sqrtf(cs) + EPSI), 0.0f);
    }

    float c4[4] = {0.f, 0.f, 0.f, 0.f};
    float uu0[4], uu1[4], hh0[4], hh1[4];
    float nu0[4], nu1[4], nh0[4], nh1[4];

    int pair0 = rev ? (NPAIR - 1 - blockIdx.x) : blockIdx.x;
    {
        const size_t b = (size_t)pair0 * 2 * NCOL + col;
        ld4h(g_u + b, uu0);  ld4h(g_u + b + NCOL, uu1);
        ld4h(g_h + b, hh0);  ld4h(g_h + b + NCOL, hh1);
    }

    int it = 0;
    for (int w = blockIdx.x; w < NPAIR; w += GRID, ++it) {
        const int cur  = it & 1;
        const int pair = rev ? (NPAIR - 1 - w) : w;

        float e0[4], e1[4], zp0[4], zp1[4];
#pragma unroll
        for (int j = 0; j < 4; ++j) {
            float s  = soft(uu0[j]);
            float X  = sc[j] * s;
            zp0[j]   = uu0[j] - X;                          // Z_k
            float sx = (X == 0.0f) ? SQMIN : sqrtf(X);      // MIN_VALUE substitution
            e0[j]    = hh0[j] * sx * __expf(-0.5f * zp0[j]);
        }
#pragma unroll
        for (int j = 0; j < 4; ++j) {
            float s  = soft(uu1[j]);
            float X  = sc[j] * s;
            zp1[j]   = uu1[j] - X;
            float sx = (X == 0.0f) ? SQMIN : sqrtf(X);
            e1[j]    = hh1[j] * sx * __expf(-0.5f * zp1[j]);
        }
        float p0 = wredsum((e0[0] + e0[1]) + (e0[2] + e0[3]));
        float p1 = wredsum((e1[0] + e1[1]) + (e1[2] + e1[3]));
        if (lane == 0) { sp[cur][0][wid] = p0; sp[cur][1][wid] = p1; }

        int nw = w + GRID; if (nw >= NPAIR) nw = w;          // safe redundant prefetch
        {
            const int npair = rev ? (NPAIR - 1 - nw) : nw;
            const size_t nb = (size_t)npair * 2 * NCOL + col;
            ld4h(g_u + nb, nu0);  ld4h(g_u + nb + NCOL, nu1);
            ld4h(g_h + nb, nh0);  ld4h(g_h + nb + NCOL, nh1);
        }
        __syncthreads();
        float S0 = 0.f, S1 = 0.f;
#pragma unroll
        for (int ww = 0; ww < NWARP; ++ww) { S0 += sp[cur][0][ww]; S1 += sp[cur][1][ww]; }
        const float i0 = __fdividef(1.0f, S0);
        const float i1 = __fdividef(1.0f, S1);

        const size_t base = (size_t)pair * 2 * NCOL + col;
        float rn0[4], rn1[4];
#pragma unroll
        for (int j = 0; j < 4; ++j) { rn0[j] = e0[j] * i0; rn1[j] = e1[j] * i1; }

        if (last) {
            *(float4*)(out + base)        = make_float4(rn0[0], rn0[1], rn0[2], rn0[3]);
            *(float4*)(out + base + NCOL) = make_float4(rn1[0], rn1[1], rn1[2], rn1[3]);
        } else {
            float un0[4], un1[4];
#pragma unroll
            for (int j = 0; j < 4; ++j) {
                un0[j] = rn0[j] + zp0[j];                   // u_{k+1}
                un1[j] = rn1[j] + zp1[j];
                float s0 = soft(un0[j]), s1 = soft(un1[j]);
                c4[j] += s0 * s0 + s1 * s1;
            }
            st4h(g_u + base,        un0);
            st4h(g_u + base + NCOL, un1);
        }
#pragma unroll
        for (int j = 0; j < 4; ++j) {
            uu0[j] = nu0[j]; uu1[j] = nu1[j];
            hh0[j] = nh0[j]; hh1[j] = nh1[j];
        }
    }
    if (!last) {
#pragma unroll
        for (int j = 0; j < 4; ++j)
            atomicAdd(&g_cs[((size_t)(k + 1) * NCOL + col + j) * CSS], c4[j]);
    }
}

extern "C" void kernel_launch(void* const* d_in, const int* in_sizes, int n_in,
                              void* d_out, int out_size) {
    const float* r0 = (const float*)d_in[0];
    float* out = (float*)d_out;

    k_zero<<<NIT, NCOL>>>();
    k_init<<<GRID, NTHR>>>(r0);
    for (int k = 1; k < NIT; ++k)
        k_step<<<GRID, NTHR>>>(out, k, k & 1, (k == NIT - 1) ? 1 : 0);
}